// round 9
// baseline (speedup 1.0000x reference)
#include <cuda_runtime.h>
#include <cuda_bf16.h>
#include <cstdint>

#define N_CELLS 50000
#define DEG 32
#define D 64
#define NEG_SLOPE 0.2f

// -------- Kernel 1: message = x @ W0 ; ns = message @ a_src ; nd = message @ a_dst
// Bit-match target (XLA-CPU on aarch64 Grace):
//   gemm (Eigen gebp): per output element, sequential fused FMA over k=0..63
//   gemv (XLA RowMajorGemv, vector width 8 = 2x NEON, fused fma):
//        8 strided partials p_i over k ≡ i (mod 8), then AddReduce halving:
//        ((p0+p4)+(p2+p6)) + ((p1+p5)+(p3+p7))
__global__ void __launch_bounds__(64) gemm_proj_kernel(
    const float* __restrict__ x,     // [N, 64]
    const float* __restrict__ W,     // [64, 64]
    const float* __restrict__ a0,    // [128, 1]
    float* __restrict__ msg,         // [N, 64]
    float* __restrict__ ns,          // [N]
    float* __restrict__ nd,          // [N]
    int n)
{
    __shared__ float xs[D];
    __shared__ float ms[D];
    __shared__ float as_s[D];
    __shared__ float ad_s[D];

    const int j = threadIdx.x;          // output column 0..63

    // W column j in registers (coalesced: consecutive j -> consecutive addresses)
    float w[D];
#pragma unroll
    for (int k = 0; k < D; k++) w[k] = W[k * D + j];
    as_s[j] = a0[j];
    ad_s[j] = a0[D + j];
    __syncthreads();

    for (int row = blockIdx.x; row < n; row += gridDim.x) {
        xs[j] = x[row * D + j];
        __syncthreads();

        // Eigen gebp order: sequential fma over k
        float acc = 0.f;
#pragma unroll
        for (int k = 0; k < D; k++) acc = fmaf(xs[k], w[k], acc);
        msg[row * D + j] = acc;
        ms[j] = acc;
        __syncthreads();

        // XLA RowMajorGemv width-8: strided fma partials + lane-halving reduce
        if (j < 2) {
            const float* __restrict__ av = (j == 0) ? as_s : ad_s;
            float p0 = 0.f, p1 = 0.f, p2 = 0.f, p3 = 0.f;
            float p4 = 0.f, p5 = 0.f, p6 = 0.f, p7 = 0.f;
#pragma unroll
            for (int k = 0; k < D; k += 8) {
                p0 = fmaf(ms[k + 0], av[k + 0], p0);
                p1 = fmaf(ms[k + 1], av[k + 1], p1);
                p2 = fmaf(ms[k + 2], av[k + 2], p2);
                p3 = fmaf(ms[k + 3], av[k + 3], p3);
                p4 = fmaf(ms[k + 4], av[k + 4], p4);
                p5 = fmaf(ms[k + 5], av[k + 5], p5);
                p6 = fmaf(ms[k + 6], av[k + 6], p6);
                p7 = fmaf(ms[k + 7], av[k + 7], p7);
            }
            // halving: (p0+p4,p1+p5,p2+p6,p3+p7) -> (q0+q2, q1+q3) -> sum
            const float q0 = __fadd_rn(p0, p4);
            const float q1 = __fadd_rn(p1, p5);
            const float q2 = __fadd_rn(p2, p6);
            const float q3 = __fadd_rn(p3, p7);
            const float r  = __fadd_rn(__fadd_rn(q0, q2), __fadd_rn(q1, q3));
            if (j == 0) ns[row] = r; else nd[row] = r;
        }
        __syncthreads();   // protect xs/ms before next iteration
    }
}

// -------- Kernel 2: per-row edge attention + gather-aggregate. One warp per row.
// row_sum and output aggregation: strictly sequential over the row's 32 edges
// (XLA scatter-add order). vals*message = rounded mul then rounded add (no fma).
__global__ void __launch_bounds__(256) gat_aggregate_kernel(
    const float* __restrict__ msg,   // [N, 64]
    const float* __restrict__ ns,    // [N]
    const float* __restrict__ nd,    // [N]
    const int*   __restrict__ cols,  // [N*32]
    const float* __restrict__ nv,    // [N*32]
    float* __restrict__ out,         // [N, 64]
    int n)
{
    const int gwarp = (blockIdx.x * blockDim.x + threadIdx.x) >> 5;
    const int lane = threadIdx.x & 31;
    if (gwarp >= n) return;
    const int row = gwarp;

    const int eidx = row * DEG + lane;
    const int col = cols[eidx];

    float e = __fadd_rn(ns[row], __ldg(&nd[col]));
    e = (e >= 0.f) ? e : __fmul_rn(NEG_SLOPE, e);

    // row sum: strictly sequential in edge order
    float S = 0.f;
#pragma unroll
    for (int k = 0; k < DEG; k++)
        S = __fadd_rn(S, __shfl_sync(0xFFFFFFFFu, e, k));

    const float att = __fdiv_rn(e, S);
    const float wgt = __fmul_rn(nv[eidx], att);   // vals = nv * att

    // Phase B: lane owns columns (2*lane, 2*lane+1); sequential over edges,
    // rounded mul then rounded add
    const float2* __restrict__ m2 = (const float2*)msg;
    float2 acc = make_float2(0.f, 0.f);
#pragma unroll
    for (int k = 0; k < DEG; k++) {
        const float wk = __shfl_sync(0xFFFFFFFFu, wgt, k);
        const int   ck = __shfl_sync(0xFFFFFFFFu, col, k);
        const float2 m = m2[ck * (D / 2) + lane];
        acc.x = __fadd_rn(acc.x, __fmul_rn(wk, m.x));
        acc.y = __fadd_rn(acc.y, __fmul_rn(wk, m.y));
    }
    acc.x = fmaxf(acc.x, 0.f);
    acc.y = fmaxf(acc.y, 0.f);
    ((float2*)out)[row * (D / 2) + lane] = acc;
}

// Scratch for intermediates (no cudaMalloc allowed)
__device__ float g_msg[N_CELLS * D];
__device__ float g_ns[N_CELLS];
__device__ float g_nd[N_CELLS];

extern "C" void kernel_launch(void* const* d_in, const int* in_sizes, int n_in,
                              void* d_out, int out_size) {
    const float* x    = (const float*)d_in[0];   // x_source [N,64]
    // d_in[1] = edge_rows (implicit: repeat(arange(N), 32)) — unused
    const int*   cols = (const int*)  d_in[2];   // edge_cols [N*32]
    const float* nv   = (const float*)d_in[3];   // neighborhood_values [N*32]
    const float* W0   = (const float*)d_in[4];   // [64,64]
    const float* a0   = (const float*)d_in[5];   // [128,1]
    float* out = (float*)d_out;

    float* msg; float* ns; float* nd;
    cudaGetSymbolAddress((void**)&msg, g_msg);
    cudaGetSymbolAddress((void**)&ns,  g_ns);
    cudaGetSymbolAddress((void**)&nd,  g_nd);

    const int n = N_CELLS;

    // Kernel 1: grid-stride rows
    int grid1 = 2368;
    if (grid1 > n) grid1 = n;
    gemm_proj_kernel<<<grid1, 64>>>(x, W0, a0, msg, ns, nd, n);

    // Kernel 2: one warp per row, 8 rows per 256-thread block
    int grid2 = (n + 7) / 8;
    gat_aggregate_kernel<<<grid2, 256>>>(msg, ns, nd, cols, nv, out, n);
}

// round 10
// speedup vs baseline: 1.6999x; 1.6999x over previous
#include <cuda_runtime.h>
#include <cuda_bf16.h>
#include <cstdint>

#define N_CELLS 50000
#define DEG 32
#define D 64
#define NEG_SLOPE 0.2f
#define ROWS_PER_ITER 4

// -------- Kernel 1: message = x @ W0 ; ns = message @ a_src ; nd = message @ a_dst
// Bit-exact orders (validated R9):
//   gemm: per output element, sequential fused FMA over k=0..63
//   gemv: width-8 strided fma partials, AddReduce halving
//         ((p0+p4)+(p2+p6)) + ((p1+p5)+(p3+p7))
// Perf: 4 rows per 256-thread block iteration (amortized barriers, 4x ILP).
__global__ void __launch_bounds__(256) gemm_proj_kernel(
    const float* __restrict__ x,     // [N, 64]
    const float* __restrict__ W,     // [64, 64]
    const float* __restrict__ a0,    // [128, 1]
    float* __restrict__ msg,         // [N, 64]
    float* __restrict__ ns,          // [N]
    float* __restrict__ nd,          // [N]
    int n)
{
    __shared__ float xs[ROWS_PER_ITER][D];
    __shared__ float ms[ROWS_PER_ITER][D];
    __shared__ float as_s[D];
    __shared__ float ad_s[D];

    const int tid = threadIdx.x;
    const int j = tid & 63;             // output column
    const int r = tid >> 6;             // row slot 0..3

    // W column j in registers (coalesced; 4 threads share a column)
    float w[D];
#pragma unroll
    for (int k = 0; k < D; k++) w[k] = W[k * D + j];
    if (tid < D) as_s[tid] = a0[tid];
    else if (tid < 2 * D) ad_s[tid - D] = a0[tid];
    __syncthreads();

    // N_CELLS % 4 == 0, so base+r is always in range when base < n
    for (int base = blockIdx.x * ROWS_PER_ITER; base < n;
         base += gridDim.x * ROWS_PER_ITER) {
        const int row = base + r;
        xs[r][j] = x[row * D + j];
        __syncthreads();

        // Eigen gebp order: sequential fma over k (broadcast reads, no conflicts)
        float acc = 0.f;
#pragma unroll
        for (int k = 0; k < D; k++) acc = fmaf(xs[r][k], w[k], acc);
        msg[row * D + j] = acc;
        ms[r][j] = acc;
        __syncthreads();

        // gemv: 8 threads (4 rows x {ns, nd}), width-8 fma partials + halving
        if (tid < 2 * ROWS_PER_ITER) {
            const int rr = tid >> 1;
            const float* __restrict__ av = (tid & 1) ? ad_s : as_s;
            const float* __restrict__ m = ms[rr];
            float p0 = 0.f, p1 = 0.f, p2 = 0.f, p3 = 0.f;
            float p4 = 0.f, p5 = 0.f, p6 = 0.f, p7 = 0.f;
#pragma unroll
            for (int k = 0; k < D; k += 8) {
                p0 = fmaf(m[k + 0], av[k + 0], p0);
                p1 = fmaf(m[k + 1], av[k + 1], p1);
                p2 = fmaf(m[k + 2], av[k + 2], p2);
                p3 = fmaf(m[k + 3], av[k + 3], p3);
                p4 = fmaf(m[k + 4], av[k + 4], p4);
                p5 = fmaf(m[k + 5], av[k + 5], p5);
                p6 = fmaf(m[k + 6], av[k + 6], p6);
                p7 = fmaf(m[k + 7], av[k + 7], p7);
            }
            const float q0 = __fadd_rn(p0, p4);
            const float q1 = __fadd_rn(p1, p5);
            const float q2 = __fadd_rn(p2, p6);
            const float q3 = __fadd_rn(p3, p7);
            const float rv = __fadd_rn(__fadd_rn(q0, q2), __fadd_rn(q1, q3));
            if (tid & 1) nd[base + rr] = rv; else ns[base + rr] = rv;
        }
        __syncthreads();
    }
}

// -------- Kernel 2: per-row edge attention + gather-aggregate. One warp per row.
// S: strictly sequential in edge order (amplified -> must bit-match).
// Output accumulation: fma chain stays in sequential k order (bit-exact);
// gathers are batched 8-deep for MLP (load scheduling only).
__global__ void __launch_bounds__(256) gat_aggregate_kernel(
    const float* __restrict__ msg,   // [N, 64]
    const float* __restrict__ ns,    // [N]
    const float* __restrict__ nd,    // [N]
    const int*   __restrict__ cols,  // [N*32]
    const float* __restrict__ nv,    // [N*32]
    float* __restrict__ out,         // [N, 64]
    int n)
{
    const int gwarp = (blockIdx.x * blockDim.x + threadIdx.x) >> 5;
    const int lane = threadIdx.x & 31;
    if (gwarp >= n) return;
    const int row = gwarp;

    const int eidx = row * DEG + lane;
    const int col = cols[eidx];

    float e = __fadd_rn(ns[row], __ldg(&nd[col]));
    e = (e >= 0.f) ? e : __fmul_rn(NEG_SLOPE, e);

    // row sum: strictly sequential in edge order
    float S = 0.f;
#pragma unroll
    for (int k = 0; k < DEG; k++)
        S = __fadd_rn(S, __shfl_sync(0xFFFFFFFFu, e, k));

    const float att = __fdiv_rn(e, S);
    const float wgt = __fmul_rn(nv[eidx], att);   // vals = nv * att

    // Batched gather: 8 loads in flight, fma applied in sequential k order
    const float2* __restrict__ m2 = (const float2*)msg;
    float2 acc = make_float2(0.f, 0.f);
#pragma unroll
    for (int kb = 0; kb < DEG; kb += 8) {
        int    c[8];
        float  wv[8];
        float2 m[8];
#pragma unroll
        for (int i = 0; i < 8; i++) {
            c[i] = __shfl_sync(0xFFFFFFFFu, col, kb + i);
            wv[i] = __shfl_sync(0xFFFFFFFFu, wgt, kb + i);
        }
#pragma unroll
        for (int i = 0; i < 8; i++)
            m[i] = m2[c[i] * (D / 2) + lane];
#pragma unroll
        for (int i = 0; i < 8; i++) {
            acc.x = __fadd_rn(acc.x, __fmul_rn(wv[i], m[i].x));
            acc.y = __fadd_rn(acc.y, __fmul_rn(wv[i], m[i].y));
        }
    }
    acc.x = fmaxf(acc.x, 0.f);
    acc.y = fmaxf(acc.y, 0.f);
    ((float2*)out)[row * (D / 2) + lane] = acc;
}

// Scratch for intermediates (no cudaMalloc allowed)
__device__ float g_msg[N_CELLS * D];
__device__ float g_ns[N_CELLS];
__device__ float g_nd[N_CELLS];

extern "C" void kernel_launch(void* const* d_in, const int* in_sizes, int n_in,
                              void* d_out, int out_size) {
    const float* x    = (const float*)d_in[0];   // x_source [N,64]
    // d_in[1] = edge_rows (implicit: repeat(arange(N), 32)) — unused
    const int*   cols = (const int*)  d_in[2];   // edge_cols [N*32]
    const float* nv   = (const float*)d_in[3];   // neighborhood_values [N*32]
    const float* W0   = (const float*)d_in[4];   // [64,64]
    const float* a0   = (const float*)d_in[5];   // [128,1]
    float* out = (float*)d_out;

    float* msg; float* ns; float* nd;
    cudaGetSymbolAddress((void**)&msg, g_msg);
    cudaGetSymbolAddress((void**)&ns,  g_ns);
    cudaGetSymbolAddress((void**)&nd,  g_nd);

    const int n = N_CELLS;

    // Kernel 1: 4 rows per block-iteration; ~8 blocks/SM
    int grid1 = 1184;
    gemm_proj_kernel<<<grid1, 256>>>(x, W0, a0, msg, ns, nd, n);

    // Kernel 2: one warp per row, 8 rows per 256-thread block
    int grid2 = (n + 7) / 8;
    gat_aggregate_kernel<<<grid2, 256>>>(msg, ns, nd, cols, nv, out, n);
}

// round 12
// speedup vs baseline: 2.4748x; 1.4558x over previous
#include <cuda_runtime.h>
#include <cuda_bf16.h>
#include <cstdint>

#define N_CELLS 50000
#define DEG 32
#define D 64
#define NEG_SLOPE 0.2f

typedef unsigned long long u64;

// ---- packed f32x2 helpers (lane-wise .rn == scalar ops, bit-exact) ----
__device__ __forceinline__ u64 packdup(float v) {
    u64 r; asm("mov.b64 %0, {%1, %1};" : "=l"(r) : "f"(v)); return r;
}
__device__ __forceinline__ void unpack2(u64 v, float& a, float& b) {
    asm("mov.b64 {%0, %1}, %2;" : "=f"(a), "=f"(b) : "l"(v));
}
__device__ __forceinline__ u64 fma2(u64 a, u64 b, u64 c) {
    u64 r; asm("fma.rn.f32x2 %0, %1, %2, %3;" : "=l"(r) : "l"(a), "l"(b), "l"(c)); return r;
}
__device__ __forceinline__ u64 mul2(u64 a, u64 b) {
    u64 r; asm("mul.rn.f32x2 %0, %1, %2;" : "=l"(r) : "l"(a), "l"(b)); return r;
}
__device__ __forceinline__ u64 add2(u64 a, u64 b) {
    u64 r; asm("add.rn.f32x2 %0, %1, %2;" : "=l"(r) : "l"(a), "l"(b)); return r;
}

// -------- Kernel 1: thread-per-row. message = x @ W0 ; ns/nd = message @ a.
// Bit-exact orders (validated R9):
//   gemm: per output element, sequential fused FMA over k=0..63
//         (packed f32x2: each lane is an independent sequential-fma chain)
//   gemv: width-8 strided fma partials, AddReduce halving
//         ((p0+p4)+(p2+p6)) + ((p1+p5)+(p3+p7))
__global__ void __launch_bounds__(128) gemm_proj_kernel(
    const float* __restrict__ x,     // [N, 64]
    const float* __restrict__ W,     // [64, 64]
    const float* __restrict__ a0,    // [128, 1]
    float* __restrict__ msg,         // [N, 64]
    float* __restrict__ ns,          // [N]
    float* __restrict__ nd,          // [N]
    int n)
{
    __shared__ float Wsh[D * D];     // 16 KB, native row-major [k][j]
    __shared__ float ash[2 * D];

    const int tid = threadIdx.x;
    for (int i = tid; i < D * D; i += 128) Wsh[i] = W[i];
    if (tid < 2 * D) ash[tid] = a0[tid];
    __syncthreads();

    const int row = blockIdx.x * 128 + tid;
    if (row >= n) return;

    // 32 packed accumulators: acc[m] = cols {2m, 2m+1}
    u64 acc[32];
#pragma unroll
    for (int m = 0; m < 32; m++) acc[m] = 0ull;

    const float4* __restrict__ xr = (const float4*)(x + (size_t)row * D);
#pragma unroll
    for (int kc = 0; kc < 16; kc++) {
        const float4 xv = xr[kc];
        const float xk[4] = {xv.x, xv.y, xv.z, xv.w};
#pragma unroll
        for (int kk = 0; kk < 4; kk++) {
            const int k = kc * 4 + kk;
            const u64 xd = packdup(xk[kk]);
            const ulonglong2* __restrict__ wr = (const ulonglong2*)(Wsh + k * D);
#pragma unroll
            for (int m = 0; m < 16; m++) {
                const ulonglong2 wv = wr[m];     // broadcast LDS.128
                acc[2 * m]     = fma2(xd, wv.x, acc[2 * m]);
                acc[2 * m + 1] = fma2(xd, wv.y, acc[2 * m + 1]);
            }
        }
    }

    // store message row (128-bit stores)
    ulonglong2* __restrict__ mo = (ulonglong2*)(msg + (size_t)row * D);
#pragma unroll
    for (int m = 0; m < 16; m++) {
        ulonglong2 v; v.x = acc[2 * m]; v.y = acc[2 * m + 1];
        mo[m] = v;
    }

    // gemv (both ns and nd), exact R9 order:
    // pp[jp&3] packs partials: pp0={p0,p1} pp1={p2,p3} pp2={p4,p5} pp3={p6,p7}
    const u64* __restrict__ as2 = (const u64*)ash;        // a_src pairs
    const u64* __restrict__ ad2 = (const u64*)(ash + D);  // a_dst pairs
    u64 pps[4] = {0ull, 0ull, 0ull, 0ull};
    u64 ppd[4] = {0ull, 0ull, 0ull, 0ull};
#pragma unroll
    for (int jp = 0; jp < 32; jp++) {
        pps[jp & 3] = fma2(acc[jp], as2[jp], pps[jp & 3]);
        ppd[jp & 3] = fma2(acc[jp], ad2[jp], ppd[jp & 3]);
    }
    // {q0,q1} = pp0+pp2 ; {q2,q3} = pp1+pp3 ; r = (q0+q2) + (q1+q3)
    {
        const u64 q01 = add2(pps[0], pps[2]);
        const u64 q23 = add2(pps[1], pps[3]);
        const u64 rr  = add2(q01, q23);
        float lo, hi; unpack2(rr, lo, hi);
        ns[row] = __fadd_rn(lo, hi);
    }
    {
        const u64 q01 = add2(ppd[0], ppd[2]);
        const u64 q23 = add2(ppd[1], ppd[3]);
        const u64 rr  = add2(q01, q23);
        float lo, hi; unpack2(rr, lo, hi);
        nd[row] = __fadd_rn(lo, hi);
    }
}

// -------- Kernel 2: per-row edge attention + gather-aggregate. One warp per row.
// S: strictly sequential in edge order (amplified -> must bit-match).
// Epilogue: mul.rn.f32x2 + add.rn.f32x2 per edge (lane-wise == scalar mul/add),
// applied in ascending edge order; gathers batched 8-deep for MLP.
__global__ void __launch_bounds__(256) gat_aggregate_kernel(
    const float* __restrict__ msg,   // [N, 64]
    const float* __restrict__ ns,    // [N]
    const float* __restrict__ nd,    // [N]
    const int*   __restrict__ cols,  // [N*32]
    const float* __restrict__ nv,    // [N*32]
    float* __restrict__ out,         // [N, 64]
    int n)
{
    __shared__ float2 cw[8][DEG];    // per-warp staged {col, wgt}

    const int wid = threadIdx.x >> 5;
    const int lane = threadIdx.x & 31;
    const int row = blockIdx.x * 8 + wid;
    if (row >= n) return;

    const int eidx = row * DEG + lane;
    const int col = cols[eidx];

    float e = __fadd_rn(ns[row], __ldg(&nd[col]));
    e = (e >= 0.f) ? e : __fmul_rn(NEG_SLOPE, e);

    // row sum: strictly sequential in edge order
    float S = 0.f;
#pragma unroll
    for (int k = 0; k < DEG; k++)
        S = __fadd_rn(S, __shfl_sync(0xFFFFFFFFu, e, k));

    const float att = __fdiv_rn(e, S);
    const float wgt = __fmul_rn(nv[eidx], att);   // vals = nv * att

    cw[wid][lane] = make_float2(__int_as_float(col), wgt);
    __syncwarp();

    const u64* __restrict__ m2 = (const u64*)msg;  // packed col-pairs
    u64 acc = 0ull;
#pragma unroll
    for (int kb = 0; kb < DEG; kb += 8) {
        int c[8]; u64 w2[8];
#pragma unroll
        for (int i = 0; i < 8; i++) {
            const float2 t = cw[wid][kb + i];      // broadcast LDS.64
            c[i] = __float_as_int(t.x);
            w2[i] = packdup(t.y);
        }
        u64 m[8];
#pragma unroll
        for (int i = 0; i < 8; i++)
            m[i] = m2[(size_t)c[i] * (D / 2) + lane];
#pragma unroll
        for (int i = 0; i < 8; i++)
            acc = add2(acc, mul2(w2[i], m[i]));    // ascending edge order
    }
    float ax, ay; unpack2(acc, ax, ay);
    ax = fmaxf(ax, 0.f);
    ay = fmaxf(ay, 0.f);
    ((float2*)out)[(size_t)row * (D / 2) + lane] = make_float2(ax, ay);
}

// Scratch for intermediates (no cudaMalloc allowed)
__device__ float g_msg[N_CELLS * D];
__device__ float g_ns[N_CELLS];
__device__ float g_nd[N_CELLS];

extern "C" void kernel_launch(void* const* d_in, const int* in_sizes, int n_in,
                              void* d_out, int out_size) {
    const float* x    = (const float*)d_in[0];   // x_source [N,64]
    // d_in[1] = edge_rows (implicit: repeat(arange(N), 32)) — unused
    const int*   cols = (const int*)  d_in[2];   // edge_cols [N*32]
    const float* nv   = (const float*)d_in[3];   // neighborhood_values [N*32]
    const float* W0   = (const float*)d_in[4];   // [64,64]
    const float* a0   = (const float*)d_in[5];   // [128,1]
    float* out = (float*)d_out;

    float* msg; float* ns; float* nd;
    cudaGetSymbolAddress((void**)&msg, g_msg);
    cudaGetSymbolAddress((void**)&ns,  g_ns);
    cudaGetSymbolAddress((void**)&nd,  g_nd);

    const int n = N_CELLS;

    // Kernel 1: thread-per-row
    int grid1 = (n + 127) / 128;
    gemm_proj_kernel<<<grid1, 128>>>(x, W0, a0, msg, ns, nd, n);

    // Kernel 2: one warp per row, 8 rows per 256-thread block
    int grid2 = (n + 7) / 8;
    gat_aggregate_kernel<<<grid2, 256>>>(msg, ns, nd, cols, nv, out, n);
}

// round 13
// speedup vs baseline: 2.5584x; 1.0338x over previous
#include <cuda_runtime.h>
#include <cuda_bf16.h>
#include <cstdint>

#define N_CELLS 50000
#define DEG 32
#define D 64
#define NEG_SLOPE 0.2f
#define XPAD 68   // padded row stride (floats): %4==0 for LDS.128 alignment

typedef unsigned long long u64;

// ---- packed f32x2 helpers (lane-wise .rn == scalar ops, bit-exact) ----
__device__ __forceinline__ u64 packdup(float v) {
    u64 r; asm("mov.b64 %0, {%1, %1};" : "=l"(r) : "f"(v)); return r;
}
__device__ __forceinline__ void unpack2(u64 v, float& a, float& b) {
    asm("mov.b64 {%0, %1}, %2;" : "=f"(a), "=f"(b) : "l"(v));
}
__device__ __forceinline__ u64 fma2(u64 a, u64 b, u64 c) {
    u64 r; asm("fma.rn.f32x2 %0, %1, %2, %3;" : "=l"(r) : "l"(a), "l"(b), "l"(c)); return r;
}
__device__ __forceinline__ u64 mul2(u64 a, u64 b) {
    u64 r; asm("mul.rn.f32x2 %0, %1, %2;" : "=l"(r) : "l"(a), "l"(b)); return r;
}
__device__ __forceinline__ u64 add2(u64 a, u64 b) {
    u64 r; asm("add.rn.f32x2 %0, %1, %2;" : "=l"(r) : "l"(a), "l"(b)); return r;
}

// -------- Kernel 1: thread-per-row, smem-staged I/O at both boundaries.
// Bit-exact orders (validated R9/R12):
//   gemm: per output element, sequential fused FMA over k=0..63 (f32x2 lanes)
//   gemv: width-8 strided fma partials, AddReduce halving
//         ((p0+p4)+(p2+p6)) + ((p1+p5)+(p3+p7))
__global__ void __launch_bounds__(128) gemm_proj_kernel(
    const float* __restrict__ x,     // [N, 64]
    const float* __restrict__ W,     // [64, 64]
    const float* __restrict__ a0,    // [128, 1]
    float* __restrict__ msg,         // [N, 64]
    float* __restrict__ ns,          // [N]
    float* __restrict__ nd,          // [N]
    int n)
{
    __shared__ __align__(16) float Wsh[D * D];       // 16 KB, row-major [k][j]
    __shared__ __align__(16) float ash[2 * D];
    __shared__ __align__(16) float xsh[128 * XPAD];  // staged x rows / msg staging

    const int tid = threadIdx.x;
    const int base = blockIdx.x * 128;
    const int rows_here = min(128, n - base);

    for (int i = tid; i < D * D; i += 128) Wsh[i] = W[i];
    if (tid < 2 * D) ash[tid] = a0[tid];
    // coalesced x load -> padded smem rows
    for (int idx = tid; idx < rows_here * D; idx += 128) {
        const int r = idx >> 6, c = idx & 63;
        xsh[r * XPAD + c] = x[(size_t)base * D + idx];
    }
    __syncthreads();

    const bool active = tid < rows_here;
    u64 acc[32];
    if (active) {
#pragma unroll
        for (int m = 0; m < 32; m++) acc[m] = 0ull;

        // own row into registers (16B-aligned LDS.128)
        float4 xr[16];
        const float4* __restrict__ xrow = (const float4*)(xsh + tid * XPAD);
#pragma unroll
        for (int i = 0; i < 16; i++) xr[i] = xrow[i];

#pragma unroll
        for (int kc = 0; kc < 16; kc++) {
            const float xk[4] = {xr[kc].x, xr[kc].y, xr[kc].z, xr[kc].w};
#pragma unroll
            for (int kk = 0; kk < 4; kk++) {
                const u64 xd = packdup(xk[kk]);
                const ulonglong2* __restrict__ wr =
                    (const ulonglong2*)(Wsh + (kc * 4 + kk) * D);
#pragma unroll
                for (int m = 0; m < 16; m++) {
                    const ulonglong2 wv = wr[m];   // broadcast LDS.128
                    acc[2 * m]     = fma2(xd, wv.x, acc[2 * m]);
                    acc[2 * m + 1] = fma2(xd, wv.y, acc[2 * m + 1]);
                }
            }
        }

        // gemv (ns and nd), exact R9 order:
        // pp0={p0,p1} pp1={p2,p3} pp2={p4,p5} pp3={p6,p7}
        const u64* __restrict__ as2 = (const u64*)ash;
        const u64* __restrict__ ad2 = (const u64*)(ash + D);
        u64 pps[4] = {0ull, 0ull, 0ull, 0ull};
        u64 ppd[4] = {0ull, 0ull, 0ull, 0ull};
#pragma unroll
        for (int jp = 0; jp < 32; jp++) {
            pps[jp & 3] = fma2(acc[jp], as2[jp], pps[jp & 3]);
            ppd[jp & 3] = fma2(acc[jp], ad2[jp], ppd[jp & 3]);
        }
        {
            const u64 q01 = add2(pps[0], pps[2]);
            const u64 q23 = add2(pps[1], pps[3]);
            const u64 rr  = add2(q01, q23);
            float lo, hi; unpack2(rr, lo, hi);
            ns[base + tid] = __fadd_rn(lo, hi);
        }
        {
            const u64 q01 = add2(ppd[0], ppd[2]);
            const u64 q23 = add2(ppd[1], ppd[3]);
            const u64 rr  = add2(q01, q23);
            float lo, hi; unpack2(rr, lo, hi);
            nd[base + tid] = __fadd_rn(lo, hi);
        }
    }
    __syncthreads();   // all xsh reads complete

    // park acc rows back into xsh (same [r*XPAD .. r*XPAD+64) footprint)
    if (active) {
        u64* __restrict__ stage = (u64*)xsh + tid * (XPAD / 2);
#pragma unroll
        for (int m = 0; m < 32; m++) stage[m] = acc[m];
    }
    __syncthreads();

    // coalesced msg store (float4 sweep)
    {
        float4* __restrict__ dst4 = (float4*)(msg + (size_t)base * D);
        const int total4 = rows_here * (D / 4);
        for (int q = tid; q < total4; q += 128) {
            const int r = q >> 4, c4 = q & 15;
            dst4[q] = *(const float4*)(xsh + r * XPAD + c4 * 4);
        }
    }
}

// -------- Kernel 2: per-row edge attention + gather-aggregate. One warp per row.
// At the chip LTS cap (~409MB of L2 gathers) — unchanged from R12.
__global__ void __launch_bounds__(256) gat_aggregate_kernel(
    const float* __restrict__ msg,   // [N, 64]
    const float* __restrict__ ns,    // [N]
    const float* __restrict__ nd,    // [N]
    const int*   __restrict__ cols,  // [N*32]
    const float* __restrict__ nv,    // [N*32]
    float* __restrict__ out,         // [N, 64]
    int n)
{
    __shared__ float2 cw[8][DEG];    // per-warp staged {col, wgt}

    const int wid = threadIdx.x >> 5;
    const int lane = threadIdx.x & 31;
    const int row = blockIdx.x * 8 + wid;
    if (row >= n) return;

    const int eidx = row * DEG + lane;
    const int col = cols[eidx];

    float e = __fadd_rn(ns[row], __ldg(&nd[col]));
    e = (e >= 0.f) ? e : __fmul_rn(NEG_SLOPE, e);

    // row sum: strictly sequential in edge order
    float S = 0.f;
#pragma unroll
    for (int k = 0; k < DEG; k++)
        S = __fadd_rn(S, __shfl_sync(0xFFFFFFFFu, e, k));

    const float att = __fdiv_rn(e, S);
    const float wgt = __fmul_rn(nv[eidx], att);   // vals = nv * att

    cw[wid][lane] = make_float2(__int_as_float(col), wgt);
    __syncwarp();

    const u64* __restrict__ m2 = (const u64*)msg;  // packed col-pairs
    u64 acc = 0ull;
#pragma unroll
    for (int kb = 0; kb < DEG; kb += 8) {
        int c[8]; u64 w2[8];
#pragma unroll
        for (int i = 0; i < 8; i++) {
            const float2 t = cw[wid][kb + i];      // broadcast LDS.64
            c[i] = __float_as_int(t.x);
            w2[i] = packdup(t.y);
        }
        u64 m[8];
#pragma unroll
        for (int i = 0; i < 8; i++)
            m[i] = m2[(size_t)c[i] * (D / 2) + lane];
#pragma unroll
        for (int i = 0; i < 8; i++)
            acc = add2(acc, mul2(w2[i], m[i]));    // ascending edge order
    }
    float ax, ay; unpack2(acc, ax, ay);
    ax = fmaxf(ax, 0.f);
    ay = fmaxf(ay, 0.f);
    ((float2*)out)[(size_t)row * (D / 2) + lane] = make_float2(ax, ay);
}

// Scratch for intermediates (no cudaMalloc allowed)
__device__ float g_msg[N_CELLS * D];
__device__ float g_ns[N_CELLS];
__device__ float g_nd[N_CELLS];

extern "C" void kernel_launch(void* const* d_in, const int* in_sizes, int n_in,
                              void* d_out, int out_size) {
    const float* x    = (const float*)d_in[0];   // x_source [N,64]
    // d_in[1] = edge_rows (implicit: repeat(arange(N), 32)) — unused
    const int*   cols = (const int*)  d_in[2];   // edge_cols [N*32]
    const float* nv   = (const float*)d_in[3];   // neighborhood_values [N*32]
    const float* W0   = (const float*)d_in[4];   // [64,64]
    const float* a0   = (const float*)d_in[5];   // [128,1]
    float* out = (float*)d_out;

    float* msg; float* ns; float* nd;
    cudaGetSymbolAddress((void**)&msg, g_msg);
    cudaGetSymbolAddress((void**)&ns,  g_ns);
    cudaGetSymbolAddress((void**)&nd,  g_nd);

    const int n = N_CELLS;

    // Kernel 1: 128 rows per 128-thread CTA, smem-staged I/O
    int grid1 = (n + 127) / 128;
    gemm_proj_kernel<<<grid1, 128>>>(x, W0, a0, msg, ns, nd, n);

    // Kernel 2: one warp per row, 8 rows per 256-thread block
    int grid2 = (n + 7) / 8;
    gat_aggregate_kernel<<<grid2, 256>>>(msg, ns, nd, cols, nv, out, n);
}